// round 1
// baseline (speedup 1.0000x reference)
#include <cuda_runtime.h>
#include <math.h>

#define BATCH 16
#define NQ 256
#define NKV 2304
#define HDIM 768
#define IMGD 1024
#define NHEADS 12
#define INTER 3072
#define HEADD 64
#define LN_EPS 1e-5f
#define ATT_SCALE 0.125f

// -------------------- scratch (device globals; no allocations allowed) -----
__device__ float g_xn[(size_t)BATCH * NKV * IMGD];          // 151 MB
__device__ float g_hn[(size_t)BATCH * NQ * HDIM];
__device__ float g_q [(size_t)BATCH * NQ * HDIM];
__device__ float g_k [(size_t)BATCH * NKV * HDIM];
__device__ float g_v [(size_t)BATCH * NKV * HDIM];
__device__ float g_sc[(size_t)BATCH * NHEADS * NQ * NKV];   // 453 MB
__device__ float g_ao[(size_t)BATCH * NQ * HDIM];
__device__ float g_o2[(size_t)BATCH * NQ * HDIM];
__device__ float g_hb[(size_t)BATCH * NQ * HDIM];
__device__ float g_t1[(size_t)BATCH * NQ * INTER];

// -------------------- LayerNorm: one block per row -------------------------
template <int COLS>
__global__ void __launch_bounds__(256) ln_kernel(
    const float* __restrict__ x, const float* __restrict__ g,
    const float* __restrict__ b, float* __restrict__ y)
{
    constexpr int PT = COLS / 256;
    const int row = blockIdx.x;
    const float* xr = x + (size_t)row * COLS;
    float* yr = y + (size_t)row * COLS;

    float v[PT];
    float s = 0.f, s2 = 0.f;
#pragma unroll
    for (int i = 0; i < PT; i++) {
        float t = xr[threadIdx.x + i * 256];
        v[i] = t; s += t; s2 += t * t;
    }
    __shared__ float red0[8], red1[8];
#pragma unroll
    for (int o = 16; o; o >>= 1) {
        s  += __shfl_xor_sync(0xffffffffu, s, o);
        s2 += __shfl_xor_sync(0xffffffffu, s2, o);
    }
    int w = threadIdx.x >> 5, l = threadIdx.x & 31;
    if (l == 0) { red0[w] = s; red1[w] = s2; }
    __syncthreads();
    s  = red0[0] + red0[1] + red0[2] + red0[3] + red0[4] + red0[5] + red0[6] + red0[7];
    s2 = red1[0] + red1[1] + red1[2] + red1[3] + red1[4] + red1[5] + red1[6] + red1[7];

    float mu  = s * (1.f / COLS);
    float var = s2 * (1.f / COLS) - mu * mu;
    float inv = rsqrtf(var + LN_EPS);
#pragma unroll
    for (int i = 0; i < PT; i++) {
        int c = threadIdx.x + i * 256;
        yr[c] = (v[i] - mu) * inv * g[c] + b[c];
    }
}

// -------------------- row softmax over NKV=2304 -----------------------------
__global__ void __launch_bounds__(256) softmax_kernel(float* __restrict__ sc)
{
    constexpr int PT = NKV / 256;  // 9
    size_t base = (size_t)blockIdx.x * NKV;
    float v[PT];
    float mx = -3.4e38f;
#pragma unroll
    for (int i = 0; i < PT; i++) {
        v[i] = sc[base + threadIdx.x + i * 256];
        mx = fmaxf(mx, v[i]);
    }
    __shared__ float redm[8], reds[8];
#pragma unroll
    for (int o = 16; o; o >>= 1) mx = fmaxf(mx, __shfl_xor_sync(0xffffffffu, mx, o));
    int w = threadIdx.x >> 5, l = threadIdx.x & 31;
    if (l == 0) redm[w] = mx;
    __syncthreads();
    mx = fmaxf(fmaxf(fmaxf(redm[0], redm[1]), fmaxf(redm[2], redm[3])),
               fmaxf(fmaxf(redm[4], redm[5]), fmaxf(redm[6], redm[7])));
    float s = 0.f;
#pragma unroll
    for (int i = 0; i < PT; i++) { v[i] = expf(v[i] - mx); s += v[i]; }
#pragma unroll
    for (int o = 16; o; o >>= 1) s += __shfl_xor_sync(0xffffffffu, s, o);
    if (l == 0) reds[w] = s;
    __syncthreads();
    s = reds[0] + reds[1] + reds[2] + reds[3] + reds[4] + reds[5] + reds[6] + reds[7];
    float inv = 1.f / s;
#pragma unroll
    for (int i = 0; i < PT; i++) sc[base + threadIdx.x + i * 256] = v[i] * inv;
}

// -------------------- templated SGEMM 128x128x8, 256 thr, 8x8/thread --------
// C[M,N] = epi(A[M,K] * B + bias)  with optional batched (b,h) offsetting.
// TRANSB=false: B is [K,N] row-major (ldb = row stride).
// TRANSB=true : B is [N,K] row-major (C = A * B^T).
// EPI: 0 = none, 1 = (x+bias)*alpha, 2 = x+bias+res, 3 = gelu_exact(x+bias)
#define BM 128
#define BN 128
#define BK 8

template <bool TRANSB, int EPI>
__global__ void __launch_bounds__(256) gemm_kernel(
    const float* __restrict__ A, const float* __restrict__ Bm,
    const float* __restrict__ bias, const float* __restrict__ res,
    float* __restrict__ C,
    int M, int N, int K, int lda, int ldb, int ldc,
    int nh,
    long long sAb, long long sAh, long long sBb, long long sBh,
    long long sCb, long long sCh,
    float alpha)
{
    const int z = blockIdx.z;
    const int zb = z / nh, zh = z % nh;
    A  += zb * sAb + zh * sAh;
    Bm += zb * sBb + zh * sBh;
    C  += zb * sCb + zh * sCh;

    __shared__ float As[BK][BM];
    __shared__ float Bs[BK][BN];

    const int tid = threadIdx.x;
    const int bm = blockIdx.y * BM;
    const int bn = blockIdx.x * BN;
    const int tx = tid & 15, ty = tid >> 4;

    const int arow = tid >> 1;            // 0..127
    const int acol = (tid & 1) << 2;      // 0 or 4
    const int bkrow = tid >> 5;           // 0..7
    const int bncol = (tid & 31) << 2;    // 0..124

    float acc[8][8];
#pragma unroll
    for (int i = 0; i < 8; i++)
#pragma unroll
        for (int j = 0; j < 8; j++) acc[i][j] = 0.f;

    for (int k0 = 0; k0 < K; k0 += BK) {
        // A tile -> As[k][m] (transposed store)
        float4 av = *(const float4*)(A + (long long)(bm + arow) * lda + (k0 + acol));
        As[acol + 0][arow] = av.x;
        As[acol + 1][arow] = av.y;
        As[acol + 2][arow] = av.z;
        As[acol + 3][arow] = av.w;
        // B tile -> Bs[k][n]
        if (!TRANSB) {
            int gn = bn + bncol;
            float4 bv = make_float4(0.f, 0.f, 0.f, 0.f);
            if (gn < N) bv = *(const float4*)(Bm + (long long)(k0 + bkrow) * ldb + gn);
            *(float4*)&Bs[bkrow][bncol] = bv;
        } else {
            int n = tid >> 1;
            int gn = bn + n;
            float4 bv = make_float4(0.f, 0.f, 0.f, 0.f);
            if (gn < N) bv = *(const float4*)(Bm + (long long)gn * ldb + (k0 + acol));
            Bs[acol + 0][n] = bv.x;
            Bs[acol + 1][n] = bv.y;
            Bs[acol + 2][n] = bv.z;
            Bs[acol + 3][n] = bv.w;
        }
        __syncthreads();
#pragma unroll
        for (int kk = 0; kk < BK; kk++) {
            float ar[8], br[8];
#pragma unroll
            for (int i = 0; i < 8; i++) ar[i] = As[kk][ty * 8 + i];
#pragma unroll
            for (int j = 0; j < 8; j++) br[j] = Bs[kk][tx * 8 + j];
#pragma unroll
            for (int i = 0; i < 8; i++)
#pragma unroll
                for (int j = 0; j < 8; j++)
                    acc[i][j] = fmaf(ar[i], br[j], acc[i][j]);
        }
        __syncthreads();
    }

#pragma unroll
    for (int i = 0; i < 8; i++) {
        int row = bm + ty * 8 + i;  // M is always a multiple of 128 here
#pragma unroll
        for (int j = 0; j < 8; j++) {
            int col = bn + tx * 8 + j;
            if (col >= N) continue;
            float val = acc[i][j];
            if (EPI == 1) {
                val = (val + bias[col]) * alpha;
            } else if (EPI == 2) {
                val = val + bias[col] + res[(long long)row * ldc + col];
            } else if (EPI == 3) {
                float u = val + bias[col];
                val = 0.5f * u * (1.f + erff(u * 0.70710678118654752f));
            }
            C[(long long)row * ldc + col] = val;
        }
    }
}

// -------------------- launch ------------------------------------------------
extern "C" void kernel_launch(void* const* d_in, const int* in_sizes, int n_in,
                              void* d_out, int out_size)
{
    const float* hs   = (const float*)d_in[0];
    const float* x    = (const float*)d_in[1];
    const float* Wq   = (const float*)d_in[2];
    const float* bq   = (const float*)d_in[3];
    const float* Wk   = (const float*)d_in[4];
    const float* bk   = (const float*)d_in[5];
    const float* Wv   = (const float*)d_in[6];
    const float* bv   = (const float*)d_in[7];
    const float* Wo   = (const float*)d_in[8];
    const float* bo   = (const float*)d_in[9];
    const float* W1   = (const float*)d_in[10];
    const float* b1   = (const float*)d_in[11];
    const float* W2   = (const float*)d_in[12];
    const float* b2   = (const float*)d_in[13];
    const float* gimg = (const float*)d_in[14];
    const float* bimg = (const float*)d_in[15];
    const float* ghid = (const float*)d_in[16];
    const float* bhid = (const float*)d_in[17];
    const float* gffn = (const float*)d_in[18];
    const float* bffn = (const float*)d_in[19];
    float* out = (float*)d_out;

    float *xn, *hn, *q, *k, *v, *sc, *ao, *o2, *hb, *t1;
    cudaGetSymbolAddress((void**)&xn, g_xn);
    cudaGetSymbolAddress((void**)&hn, g_hn);
    cudaGetSymbolAddress((void**)&q,  g_q);
    cudaGetSymbolAddress((void**)&k,  g_k);
    cudaGetSymbolAddress((void**)&v,  g_v);
    cudaGetSymbolAddress((void**)&sc, g_sc);
    cudaGetSymbolAddress((void**)&ao, g_ao);
    cudaGetSymbolAddress((void**)&o2, g_o2);
    cudaGetSymbolAddress((void**)&hb, g_hb);
    cudaGetSymbolAddress((void**)&t1, g_t1);

    const int MQ = BATCH * NQ;    // 4096
    const int MK = BATCH * NKV;   // 36864

    // 1) LayerNorms
    ln_kernel<IMGD><<<BATCH * NKV, 256>>>(x, gimg, bimg, xn);
    ln_kernel<HDIM><<<BATCH * NQ, 256>>>(hs, ghid, bhid, hn);

    // 2) q = (hn @ Wq + bq) * SCALE
    gemm_kernel<false, 1><<<dim3(HDIM / BN, MQ / BM, 1), 256>>>(
        hn, Wq, bq, nullptr, q, MQ, HDIM, HDIM, HDIM, HDIM, HDIM,
        1, 0, 0, 0, 0, 0, 0, ATT_SCALE);

    // 3) k = xn @ Wk + bk ; v = xn @ Wv + bv
    gemm_kernel<false, 1><<<dim3(HDIM / BN, MK / BM, 1), 256>>>(
        xn, Wk, bk, nullptr, k, MK, HDIM, IMGD, IMGD, HDIM, HDIM,
        1, 0, 0, 0, 0, 0, 0, 1.f);
    gemm_kernel<false, 1><<<dim3(HDIM / BN, MK / BM, 1), 256>>>(
        xn, Wv, bv, nullptr, v, MK, HDIM, IMGD, IMGD, HDIM, HDIM,
        1, 0, 0, 0, 0, 0, 0, 1.f);

    // 4) scores[z] = q_slice @ k_slice^T   (z = b*12 + h)
    gemm_kernel<true, 0><<<dim3(NKV / BN, NQ / BM, BATCH * NHEADS), 256>>>(
        q, k, nullptr, nullptr, sc, NQ, NKV, HEADD, HDIM, HDIM, NKV,
        NHEADS,
        (long long)NQ * HDIM, HEADD,
        (long long)NKV * HDIM, HEADD,
        (long long)NHEADS * NQ * NKV, (long long)NQ * NKV, 1.f);

    // 5) softmax over each of the 192*256 rows
    softmax_kernel<<<BATCH * NHEADS * NQ, 256>>>(sc);

    // 6) ao[z] = attn @ v_slice
    gemm_kernel<false, 0><<<dim3(1, NQ / BM, BATCH * NHEADS), 256>>>(
        sc, v, nullptr, nullptr, ao, NQ, HEADD, NKV, NKV, HDIM, HDIM,
        NHEADS,
        (long long)NHEADS * NQ * NKV, (long long)NQ * NKV,
        (long long)NKV * HDIM, HEADD,
        (long long)NQ * HDIM, HEADD, 1.f);

    // 7) o2 = ao @ Wo + bo + hidden_states
    gemm_kernel<false, 2><<<dim3(HDIM / BN, MQ / BM, 1), 256>>>(
        ao, Wo, bo, hs, o2, MQ, HDIM, HDIM, HDIM, HDIM, HDIM,
        1, 0, 0, 0, 0, 0, 0, 1.f);

    // 8) hb = LN(o2)
    ln_kernel<HDIM><<<BATCH * NQ, 256>>>(o2, gffn, bffn, hb);

    // 9) t1 = gelu(hb @ W1 + b1)
    gemm_kernel<false, 3><<<dim3(INTER / BN, MQ / BM, 1), 256>>>(
        hb, W1, b1, nullptr, t1, MQ, INTER, HDIM, HDIM, INTER, INTER,
        1, 0, 0, 0, 0, 0, 0, 1.f);

    // 10) out = t1 @ W2 + b2 + o2
    gemm_kernel<false, 2><<<dim3(HDIM / BN, MQ / BM, 1), 256>>>(
        t1, W2, b2, o2, out, MQ, HDIM, INTER, INTER, HDIM, HDIM,
        1, 0, 0, 0, 0, 0, 0, 1.f);
}

// round 3
// speedup vs baseline: 2.4817x; 2.4817x over previous
#include <cuda_runtime.h>
#include <cuda_bf16.h>
#include <stdint.h>
#include <math.h>

#define BATCH 16
#define NQ 256
#define NKV 2304
#define HDIM 768
#define IMGD 1024
#define NHEADS 12
#define INTER 3072
#define HEADD 64
#define LN_EPS 1e-5f
#define ATT_SCALE 0.125f

typedef __nv_bfloat16 bf16;

// -------------------- scratch (device globals) ------------------------------
__device__ bf16 g_xnh[(size_t)BATCH * NKV * IMGD];
__device__ bf16 g_xnl[(size_t)BATCH * NKV * IMGD];
__device__ bf16 g_hnh[(size_t)BATCH * NQ * HDIM];
__device__ bf16 g_hnl[(size_t)BATCH * NQ * HDIM];
__device__ bf16 g_qh [(size_t)BATCH * NQ * HDIM];
__device__ bf16 g_ql [(size_t)BATCH * NQ * HDIM];
__device__ bf16 g_kh [(size_t)BATCH * NKV * HDIM];
__device__ bf16 g_kl [(size_t)BATCH * NKV * HDIM];
__device__ bf16 g_vth[(size_t)BATCH * HDIM * NKV];
__device__ bf16 g_vtl[(size_t)BATCH * HDIM * NKV];
__device__ float g_sc[(size_t)BATCH * NHEADS * NQ * NKV];
__device__ bf16 g_ph [(size_t)BATCH * NHEADS * NQ * NKV];
__device__ bf16 g_pl [(size_t)BATCH * NHEADS * NQ * NKV];
__device__ bf16 g_aoh[(size_t)BATCH * NQ * HDIM];
__device__ bf16 g_aol[(size_t)BATCH * NQ * HDIM];
__device__ float g_o2[(size_t)BATCH * NQ * HDIM];
__device__ bf16 g_hbh[(size_t)BATCH * NQ * HDIM];
__device__ bf16 g_hbl[(size_t)BATCH * NQ * HDIM];
__device__ bf16 g_t1h[(size_t)BATCH * NQ * INTER];
__device__ bf16 g_t1l[(size_t)BATCH * NQ * INTER];
// transposed/split weights [N][K]
__device__ bf16 g_wqh[HDIM * HDIM],  g_wql[HDIM * HDIM];
__device__ bf16 g_wkvh[(HDIM * 2) * IMGD], g_wkvl[(HDIM * 2) * IMGD];
__device__ bf16 g_woh[HDIM * HDIM],  g_wol[HDIM * HDIM];
__device__ bf16 g_w1h[INTER * HDIM], g_w1l[INTER * HDIM];
__device__ bf16 g_w2h[HDIM * INTER], g_w2l[HDIM * INTER];

// -------------------- helpers ----------------------------------------------
__device__ __forceinline__ uint32_t smem_u32(const void* p) {
    uint32_t a;
    asm("{ .reg .u64 t; cvta.to.shared.u64 t, %1; cvt.u32.u64 %0, t; }" : "=r"(a) : "l"(p));
    return a;
}
__device__ __forceinline__ void ldmx4(uint32_t* r, uint32_t addr) {
    asm volatile("ldmatrix.sync.aligned.m8n8.x4.shared.b16 {%0,%1,%2,%3}, [%4];"
        : "=r"(r[0]), "=r"(r[1]), "=r"(r[2]), "=r"(r[3]) : "r"(addr));
}
__device__ __forceinline__ void mma16816(float* c, const uint32_t* a, const uint32_t* b) {
    asm volatile("mma.sync.aligned.m16n8k16.row.col.f32.bf16.bf16.f32 "
        "{%0,%1,%2,%3}, {%4,%5,%6,%7}, {%8,%9}, {%0,%1,%2,%3};"
        : "+f"(c[0]), "+f"(c[1]), "+f"(c[2]), "+f"(c[3])
        : "r"(a[0]), "r"(a[1]), "r"(a[2]), "r"(a[3]), "r"(b[0]), "r"(b[1]));
}
__device__ __forceinline__ void store_pair(float v, bf16* ph, bf16* pl, long long off) {
    bf16 h = __float2bfloat16(v);
    ph[off] = h;
    pl[off] = __float2bfloat16(v - __bfloat162float(h));
}

// ======================= bf16-split MMA GEMM ================================
// C[128, BN] = epi(A * B). A pair: [M][K] row-major bf16. B pair: [N][K].
// EPI: 0 fp32 C            (scores)
//      1 pair (x+bias)*alpha                 (q)
//      2 kv: bn<768 -> k pair (+bias); else v_t pair transposed (+res as bias)
//      3 pair x                              (ao)
//      4 fp32 x+bias+res                     (o2 / out)
//      5 pair gelu(x+bias)                   (t1)
template <int BN, int WM, int EPI>
__global__ void __launch_bounds__(256) mma_gemm(
    const bf16* __restrict__ Ah, const bf16* __restrict__ Al,
    const bf16* __restrict__ Bh, const bf16* __restrict__ Bl,
    const float* __restrict__ bias, const float* __restrict__ res,
    float* __restrict__ Cf, bf16* __restrict__ Ch, bf16* __restrict__ Cl,
    bf16* __restrict__ C2h, bf16* __restrict__ C2l,
    int K, long long lda, long long ldb, long long ldc,
    int nh, long long sAb, long long sAhh, long long sBb, long long sBh,
    long long sCb, long long sChh, float alpha)
{
    extern __shared__ char smem[];
    constexpr int WN  = 8 / WM;
    constexpr int MT  = 128 / WM;      // warp m extent
    constexpr int NT  = BN / WN;       // 32
    constexpr int MI  = MT / 16;
    constexpr int NI2 = NT / 16;       // 2
    constexpr int ASZ = 128 * 80;      // bytes (pitch 80B = 40 bf16)
    constexpr int BSZ = BN * 80;
    constexpr int STG = 2 * ASZ + 2 * BSZ;

    const int tid = threadIdx.x, wid = tid >> 5, lane = tid & 31;
    const int wm = wid % WM, wn = wid / WM;
    const int z = blockIdx.z, zb = z / nh, zh = z % nh;
    Ah += zb * sAb + zh * sAhh;  Al += zb * sAb + zh * sAhh;
    Bh += zb * sBb + zh * sBh;   Bl += zb * sBb + zh * sBh;
    const long long coff = zb * sCb + zh * sChh;
    if (EPI == 0 || EPI == 4) Cf += coff;
    if (EPI == 1 || EPI == 3 || EPI == 5) { Ch += coff; Cl += coff; }

    const long long bm = (long long)blockIdx.y * 128;
    const long long bn = (long long)blockIdx.x * BN;

    const bf16* gAh = Ah + bm * lda;
    const bf16* gAl = Al + bm * lda;
    const bf16* gBh = Bh + bn * ldb;
    const bf16* gBl = Bl + bn * ldb;

    float acc[MI][NI2 * 2][4];
#pragma unroll
    for (int i = 0; i < MI; i++)
#pragma unroll
        for (int j = 0; j < NI2 * 2; j++)
#pragma unroll
            for (int t = 0; t < 4; t++) acc[i][j][t] = 0.f;

    const uint32_t sb = smem_u32(smem);
    const int NC = K >> 5;

    auto fill = [&](int s, int c) {
        char* base = smem + s * STG;
        const long long k0 = (long long)c * 32;
#pragma unroll
        for (int i = tid; i < 128 * 4; i += 256) {
            int r = i >> 2, q = i & 3;
            *(int4*)(base + r * 80 + q * 16)       = *(const int4*)(gAh + r * lda + k0 + q * 8);
            *(int4*)(base + ASZ + r * 80 + q * 16) = *(const int4*)(gAl + r * lda + k0 + q * 8);
        }
#pragma unroll
        for (int i = tid; i < BN * 4; i += 256) {
            int r = i >> 2, q = i & 3;
            *(int4*)(base + 2 * ASZ + r * 80 + q * 16)       = *(const int4*)(gBh + r * ldb + k0 + q * 8);
            *(int4*)(base + 2 * ASZ + BSZ + r * 80 + q * 16) = *(const int4*)(gBl + r * ldb + k0 + q * 8);
        }
    };

    fill(0, 0);
    __syncthreads();

    const int a_r = (lane & 7) + ((lane >> 3) & 1) * 8;  // A: +row8 for mat1/3
    const int a_k = ((lane >> 4) & 1) * 8;               // A: +k8 for mat2/3
    const int b_r = (lane & 7) + ((lane >> 4) & 1) * 8;  // B: +n8 for mat2/3
    const int b_k = ((lane >> 3) & 1) * 8;               // B: +k8 for mat1/3

    for (int c = 0; c < NC; c++) {
        if (c + 1 < NC) fill((c + 1) & 1, c + 1);
        const uint32_t aH = sb + (c & 1) * STG;
        const uint32_t aL = aH + ASZ;
        const uint32_t bH = aH + 2 * ASZ;
        const uint32_t bL = bH + BSZ;
#pragma unroll
        for (int kk = 0; kk < 32; kk += 16) {
            uint32_t ah[MI][4], al[MI][4];
#pragma unroll
            for (int mi = 0; mi < MI; mi++) {
                uint32_t off = (uint32_t)(wm * MT + mi * 16 + a_r) * 80 + (kk + a_k) * 2;
                ldmx4(ah[mi], aH + off);
                ldmx4(al[mi], aL + off);
            }
#pragma unroll
            for (int nj = 0; nj < NI2; nj++) {
                uint32_t bhf[4], blf[4];
                uint32_t off = (uint32_t)(wn * NT + nj * 16 + b_r) * 80 + (kk + b_k) * 2;
                ldmx4(bhf, bH + off);
                ldmx4(blf, bL + off);
#pragma unroll
                for (int mi = 0; mi < MI; mi++) {
                    mma16816(acc[mi][nj * 2 + 0], ah[mi], bhf + 0);
                    mma16816(acc[mi][nj * 2 + 0], ah[mi], blf + 0);
                    mma16816(acc[mi][nj * 2 + 0], al[mi], bhf + 0);
                    mma16816(acc[mi][nj * 2 + 1], ah[mi], bhf + 2);
                    mma16816(acc[mi][nj * 2 + 1], ah[mi], blf + 2);
                    mma16816(acc[mi][nj * 2 + 1], al[mi], bhf + 2);
                }
            }
        }
        __syncthreads();
    }

    // ---- stage C into smem fp32 tile ----
    constexpr int P2 = BN + 4;
    float* tile = (float*)smem;
#pragma unroll
    for (int mi = 0; mi < MI; mi++)
#pragma unroll
        for (int j = 0; j < NI2 * 2; j++) {
            int row = wm * MT + mi * 16 + (lane >> 2);
            int col = wn * NT + j * 8 + (lane & 3) * 2;
            tile[row * P2 + col]           = acc[mi][j][0];
            tile[row * P2 + col + 1]       = acc[mi][j][1];
            tile[(row + 8) * P2 + col]     = acc[mi][j][2];
            tile[(row + 8) * P2 + col + 1] = acc[mi][j][3];
        }
    __syncthreads();

    if (EPI == 2 && bn >= 768) {
        // v region: transposed store, coalesced along tokens
        for (int idx = tid; idx < 128 * BN; idx += 256) {
            int rr = idx & 127, cc = idx >> 7;
            long long grow = bm + rr;
            long long vcol = bn + cc - 768;
            float val = tile[rr * P2 + cc] + res[vcol];
            long long b = grow / NKV, t = grow - b * NKV;
            long long off = (b * HDIM + vcol) * NKV + t;
            store_pair(val, C2h, C2l, off);
        }
        return;
    }
    for (int idx = tid; idx < 128 * BN; idx += 256) {
        int rr = idx / BN, cc = idx % BN;
        long long grow = bm + rr, gcol = bn + cc;
        float val = tile[rr * P2 + cc];
        if (EPI == 0) {
            Cf[grow * ldc + gcol] = val;
        } else if (EPI == 1) {
            store_pair((val + bias[gcol]) * alpha, Ch, Cl, grow * ldc + gcol);
        } else if (EPI == 2) {
            store_pair(val + bias[gcol], Ch, Cl, grow * (long long)HDIM + gcol);
        } else if (EPI == 3) {
            store_pair(val, Ch, Cl, grow * ldc + gcol);
        } else if (EPI == 4) {
            Cf[grow * ldc + gcol] = val + bias[gcol] + res[grow * ldc + gcol];
        } else if (EPI == 5) {
            float u = val + bias[gcol];
            store_pair(0.5f * u * (1.f + erff(u * 0.70710678118654752f)), Ch, Cl,
                       grow * ldc + gcol);
        }
    }
}

// -------------------- weight transpose + split ------------------------------
__global__ void __launch_bounds__(256) wprep(
    const float* __restrict__ W, int N,
    bf16* __restrict__ Th, bf16* __restrict__ Tl, int rowOff, int ldT)
{
    __shared__ float s[32][33];
    int n0 = blockIdx.x * 32, k0 = blockIdx.y * 32;
    int tx = threadIdx.x & 31, ty = threadIdx.x >> 5;
#pragma unroll
    for (int j = 0; j < 4; j++)
        s[ty + j * 8][tx] = W[(long long)(k0 + ty + j * 8) * N + n0 + tx];
    __syncthreads();
#pragma unroll
    for (int j = 0; j < 4; j++) {
        int n = n0 + ty + j * 8, k = k0 + tx;
        store_pair(s[tx][ty + j * 8], Th, Tl, (long long)(n + rowOff) * ldT + k);
    }
}

// -------------------- LayerNorm -> split pair -------------------------------
template <int COLS>
__global__ void __launch_bounds__(256) ln_kernel(
    const float* __restrict__ x, const float* __restrict__ g,
    const float* __restrict__ b, bf16* __restrict__ yh, bf16* __restrict__ yl)
{
    constexpr int PT = COLS / 256;
    const long long row = blockIdx.x;
    const float* xr = x + row * COLS;

    float v[PT];
    float s = 0.f, s2 = 0.f;
#pragma unroll
    for (int i = 0; i < PT; i++) {
        float t = xr[threadIdx.x + i * 256];
        v[i] = t; s += t; s2 += t * t;
    }
    __shared__ float red0[8], red1[8];
#pragma unroll
    for (int o = 16; o; o >>= 1) {
        s  += __shfl_xor_sync(0xffffffffu, s, o);
        s2 += __shfl_xor_sync(0xffffffffu, s2, o);
    }
    int w = threadIdx.x >> 5, l = threadIdx.x & 31;
    if (l == 0) { red0[w] = s; red1[w] = s2; }
    __syncthreads();
    s  = red0[0] + red0[1] + red0[2] + red0[3] + red0[4] + red0[5] + red0[6] + red0[7];
    s2 = red1[0] + red1[1] + red1[2] + red1[3] + red1[4] + red1[5] + red1[6] + red1[7];

    float mu  = s * (1.f / COLS);
    float var = s2 * (1.f / COLS) - mu * mu;
    float inv = rsqrtf(var + LN_EPS);
#pragma unroll
    for (int i = 0; i < PT; i++) {
        int c = threadIdx.x + i * 256;
        store_pair((v[i] - mu) * inv * g[c] + b[c], yh, yl, row * COLS + c);
    }
}

// -------------------- softmax -> split pair ---------------------------------
__global__ void __launch_bounds__(256) softmax_kernel(
    const float* __restrict__ sc, bf16* __restrict__ ph, bf16* __restrict__ pl)
{
    constexpr int PT = NKV / 256;
    size_t base = (size_t)blockIdx.x * NKV;
    float v[PT];
    float mx = -3.4e38f;
#pragma unroll
    for (int i = 0; i < PT; i++) {
        v[i] = sc[base + threadIdx.x + i * 256];
        mx = fmaxf(mx, v[i]);
    }
    __shared__ float redm[8], reds[8];
#pragma unroll
    for (int o = 16; o; o >>= 1) mx = fmaxf(mx, __shfl_xor_sync(0xffffffffu, mx, o));
    int w = threadIdx.x >> 5, l = threadIdx.x & 31;
    if (l == 0) redm[w] = mx;
    __syncthreads();
    mx = fmaxf(fmaxf(fmaxf(redm[0], redm[1]), fmaxf(redm[2], redm[3])),
               fmaxf(fmaxf(redm[4], redm[5]), fmaxf(redm[6], redm[7])));
    float s = 0.f;
#pragma unroll
    for (int i = 0; i < PT; i++) { v[i] = expf(v[i] - mx); s += v[i]; }
#pragma unroll
    for (int o = 16; o; o >>= 1) s += __shfl_xor_sync(0xffffffffu, s, o);
    if (l == 0) reds[w] = s;
    __syncthreads();
    s = reds[0] + reds[1] + reds[2] + reds[3] + reds[4] + reds[5] + reds[6] + reds[7];
    float inv = 1.f / s;
#pragma unroll
    for (int i = 0; i < PT; i++)
        store_pair(v[i] * inv, ph, pl, base + threadIdx.x + i * 256);
}

// -------------------- launch ------------------------------------------------
#define SMEM_G(BN) ((2 * (2 * 128 * 80 + 2 * (BN) * 80)) > (128 * ((BN) + 4) * 4) ? \
                    (2 * (2 * 128 * 80 + 2 * (BN) * 80)) : (128 * ((BN) + 4) * 4))

extern "C" void kernel_launch(void* const* d_in, const int* in_sizes, int n_in,
                              void* d_out, int out_size)
{
    const float* hs   = (const float*)d_in[0];
    const float* x    = (const float*)d_in[1];
    const float* Wq   = (const float*)d_in[2];
    const float* bq   = (const float*)d_in[3];
    const float* Wk   = (const float*)d_in[4];
    const float* bk   = (const float*)d_in[5];
    const float* Wv   = (const float*)d_in[6];
    const float* bv   = (const float*)d_in[7];
    const float* Wo   = (const float*)d_in[8];
    const float* bo   = (const float*)d_in[9];
    const float* W1   = (const float*)d_in[10];
    const float* b1   = (const float*)d_in[11];
    const float* W2   = (const float*)d_in[12];
    const float* b2   = (const float*)d_in[13];
    const float* gimg = (const float*)d_in[14];
    const float* bimg = (const float*)d_in[15];
    const float* ghid = (const float*)d_in[16];
    const float* bhid = (const float*)d_in[17];
    const float* gffn = (const float*)d_in[18];
    const float* bffn = (const float*)d_in[19];
    float* out = (float*)d_out;

    bf16 *xnh, *xnl, *hnh, *hnl, *qh, *ql, *kh, *kl, *vth, *vtl;
    bf16 *ph, *pl, *aoh, *aol, *hbh, *hbl, *t1h, *t1l;
    bf16 *wqh, *wql, *wkvh, *wkvl, *woh, *wol, *w1h, *w1l, *w2h, *w2l;
    float *sc, *o2;
    cudaGetSymbolAddress((void**)&xnh, g_xnh); cudaGetSymbolAddress((void**)&xnl, g_xnl);
    cudaGetSymbolAddress((void**)&hnh, g_hnh); cudaGetSymbolAddress((void**)&hnl, g_hnl);
    cudaGetSymbolAddress((void**)&qh,  g_qh);  cudaGetSymbolAddress((void**)&ql,  g_ql);
    cudaGetSymbolAddress((void**)&kh,  g_kh);  cudaGetSymbolAddress((void**)&kl,  g_kl);
    cudaGetSymbolAddress((void**)&vth, g_vth); cudaGetSymbolAddress((void**)&vtl, g_vtl);
    cudaGetSymbolAddress((void**)&sc,  g_sc);
    cudaGetSymbolAddress((void**)&ph,  g_ph);  cudaGetSymbolAddress((void**)&pl,  g_pl);
    cudaGetSymbolAddress((void**)&aoh, g_aoh); cudaGetSymbolAddress((void**)&aol, g_aol);
    cudaGetSymbolAddress((void**)&o2,  g_o2);
    cudaGetSymbolAddress((void**)&hbh, g_hbh); cudaGetSymbolAddress((void**)&hbl, g_hbl);
    cudaGetSymbolAddress((void**)&t1h, g_t1h); cudaGetSymbolAddress((void**)&t1l, g_t1l);
    cudaGetSymbolAddress((void**)&wqh, g_wqh); cudaGetSymbolAddress((void**)&wql, g_wql);
    cudaGetSymbolAddress((void**)&wkvh, g_wkvh); cudaGetSymbolAddress((void**)&wkvl, g_wkvl);
    cudaGetSymbolAddress((void**)&woh, g_woh); cudaGetSymbolAddress((void**)&wol, g_wol);
    cudaGetSymbolAddress((void**)&w1h, g_w1h); cudaGetSymbolAddress((void**)&w1l, g_w1l);
    cudaGetSymbolAddress((void**)&w2h, g_w2h); cudaGetSymbolAddress((void**)&w2l, g_w2l);

    const int S128 = SMEM_G(128);
    const int S64  = SMEM_G(64);
    cudaFuncSetAttribute(mma_gemm<128, 2, 0>, cudaFuncAttributeMaxDynamicSharedMemorySize, S128);
    cudaFuncSetAttribute(mma_gemm<128, 2, 1>, cudaFuncAttributeMaxDynamicSharedMemorySize, S128);
    cudaFuncSetAttribute(mma_gemm<128, 2, 2>, cudaFuncAttributeMaxDynamicSharedMemorySize, S128);
    cudaFuncSetAttribute(mma_gemm<64,  4, 3>, cudaFuncAttributeMaxDynamicSharedMemorySize, S64);
    cudaFuncSetAttribute(mma_gemm<128, 2, 4>, cudaFuncAttributeMaxDynamicSharedMemorySize, S128);
    cudaFuncSetAttribute(mma_gemm<128, 2, 5>, cudaFuncAttributeMaxDynamicSharedMemorySize, S128);

    const int MQ = BATCH * NQ;    // 4096
    const int MK = BATCH * NKV;   // 36864

    // 0) weight prep (transpose + bf16 split)
    wprep<<<dim3(HDIM / 32, HDIM / 32), 256>>>(Wq, HDIM, wqh, wql, 0, HDIM);
    wprep<<<dim3(HDIM / 32, IMGD / 32), 256>>>(Wk, HDIM, wkvh, wkvl, 0, IMGD);
    wprep<<<dim3(HDIM / 32, IMGD / 32), 256>>>(Wv, HDIM, wkvh, wkvl, HDIM, IMGD);
    wprep<<<dim3(HDIM / 32, HDIM / 32), 256>>>(Wo, HDIM, woh, wol, 0, HDIM);
    wprep<<<dim3(INTER / 32, HDIM / 32), 256>>>(W1, INTER, w1h, w1l, 0, HDIM);
    wprep<<<dim3(HDIM / 32, INTER / 32), 256>>>(W2, HDIM, w2h, w2l, 0, INTER);

    // 1) LayerNorms -> split pairs
    ln_kernel<IMGD><<<BATCH * NKV, 256>>>(x, gimg, bimg, xnh, xnl);
    ln_kernel<HDIM><<<BATCH * NQ, 256>>>(hs, ghid, bhid, hnh, hnl);

    // 2) q = (hn @ Wq + bq) * SCALE  -> pair
    mma_gemm<128, 2, 1><<<dim3(HDIM / 128, MQ / 128, 1), 256, S128>>>(
        hnh, hnl, wqh, wql, bq, nullptr, nullptr, qh, ql, nullptr, nullptr,
        HDIM, HDIM, HDIM, HDIM, 1, 0, 0, 0, 0, 0, 0, ATT_SCALE);

    // 3) [k|v] = xn @ [Wk|Wv] + [bk|bv]  -> k pair + v_t pair
    mma_gemm<128, 2, 2><<<dim3((2 * HDIM) / 128, MK / 128, 1), 256, S128>>>(
        xnh, xnl, wkvh, wkvl, bk, bv, nullptr, kh, kl, vth, vtl,
        IMGD, IMGD, IMGD, HDIM, 1, 0, 0, 0, 0, 0, 0, 1.f);

    // 4) scores[z] = q @ k^T  -> fp32
    mma_gemm<128, 2, 0><<<dim3(NKV / 128, NQ / 128, BATCH * NHEADS), 256, S128>>>(
        qh, ql, kh, kl, nullptr, nullptr, sc, nullptr, nullptr, nullptr, nullptr,
        HEADD, HDIM, HDIM, NKV, NHEADS,
        (long long)NQ * HDIM, HEADD,
        (long long)NKV * HDIM, HEADD,
        (long long)NHEADS * NQ * NKV, (long long)NQ * NKV, 1.f);

    // 5) softmax -> pair
    softmax_kernel<<<BATCH * NHEADS * NQ, 256>>>(sc, ph, pl);

    // 6) ao[z] = probs @ v  (B = v_t [64][2304]) -> pair
    mma_gemm<64, 4, 3><<<dim3(1, NQ / 128, BATCH * NHEADS), 256, S64>>>(
        ph, pl, vth, vtl, nullptr, nullptr, nullptr, aoh, aol, nullptr, nullptr,
        NKV, NKV, NKV, HDIM, NHEADS,
        (long long)NHEADS * NQ * NKV, (long long)NQ * NKV,
        (long long)HDIM * NKV, (long long)HEADD * NKV,
        (long long)NQ * HDIM, HEADD, 1.f);

    // 7) o2 = ao @ Wo + bo + hidden_states  -> fp32
    mma_gemm<128, 2, 4><<<dim3(HDIM / 128, MQ / 128, 1), 256, S128>>>(
        aoh, aol, woh, wol, bo, hs, o2, nullptr, nullptr, nullptr, nullptr,
        HDIM, HDIM, HDIM, HDIM, 1, 0, 0, 0, 0, 0, 0, 1.f);

    // 8) hb = LN(o2) -> pair
    ln_kernel<HDIM><<<BATCH * NQ, 256>>>(o2, gffn, bffn, hbh, hbl);

    // 9) t1 = gelu(hb @ W1 + b1) -> pair
    mma_gemm<128, 2, 5><<<dim3(INTER / 128, MQ / 128, 1), 256, S128>>>(
        hbh, hbl, w1h, w1l, b1, nullptr, nullptr, t1h, t1l, nullptr, nullptr,
        HDIM, HDIM, HDIM, INTER, 1, 0, 0, 0, 0, 0, 0, 1.f);

    // 10) out = t1 @ W2 + b2 + o2  -> fp32
    mma_gemm<128, 2, 4><<<dim3(HDIM / 128, MQ / 128, 1), 256, S128>>>(
        t1h, t1l, w2h, w2l, b2, o2, out, nullptr, nullptr, nullptr, nullptr,
        INTER, INTER, INTER, HDIM, 1, 0, 0, 0, 0, 0, 0, 1.f);
}

// round 4
// speedup vs baseline: 5.1362x; 2.0697x over previous
#include <cuda_runtime.h>
#include <cuda_fp16.h>
#include <stdint.h>
#include <math.h>

#define BATCH 16
#define NQ 256
#define NKV 2304
#define HDIM 768
#define IMGD 1024
#define NHEADS 12
#define INTER 3072
#define HEADD 64
#define LN_EPS 1e-5f
#define ATT_SCALE 0.125f

typedef __half f16;

// -------------------- scratch (device globals) ------------------------------
__device__ f16  g_xn[(size_t)BATCH * NKV * IMGD];
__device__ f16  g_hn[(size_t)BATCH * NQ * HDIM];
__device__ f16  g_q [(size_t)BATCH * NQ * HDIM];
__device__ f16  g_k [(size_t)BATCH * NKV * HDIM];
__device__ f16  g_vt[(size_t)BATCH * HDIM * NKV];
__device__ float g_sc[(size_t)BATCH * NHEADS * NQ * NKV];
__device__ f16  g_p [(size_t)BATCH * NHEADS * NQ * NKV];
__device__ f16  g_ao[(size_t)BATCH * NQ * HDIM];
__device__ float g_o2[(size_t)BATCH * NQ * HDIM];
__device__ f16  g_hb[(size_t)BATCH * NQ * HDIM];
__device__ f16  g_t1[(size_t)BATCH * NQ * INTER];
// transposed weights [N][K]
__device__ f16  g_wq[HDIM * HDIM];
__device__ f16  g_wkv[(HDIM * 2) * IMGD];
__device__ f16  g_wo[HDIM * HDIM];
__device__ f16  g_w1[INTER * HDIM];
__device__ f16  g_w2[HDIM * INTER];

// -------------------- helpers ----------------------------------------------
__device__ __forceinline__ uint32_t smem_u32(const void* p) {
    uint32_t a;
    asm("{ .reg .u64 t; cvta.to.shared.u64 t, %1; cvt.u32.u64 %0, t; }" : "=r"(a) : "l"(p));
    return a;
}
__device__ __forceinline__ void ldmx4(uint32_t* r, uint32_t addr) {
    asm volatile("ldmatrix.sync.aligned.m8n8.x4.shared.b16 {%0,%1,%2,%3}, [%4];"
        : "=r"(r[0]), "=r"(r[1]), "=r"(r[2]), "=r"(r[3]) : "r"(addr));
}
__device__ __forceinline__ void mma16816(float* c, const uint32_t* a, const uint32_t* b) {
    asm volatile("mma.sync.aligned.m16n8k16.row.col.f32.f16.f16.f32 "
        "{%0,%1,%2,%3}, {%4,%5,%6,%7}, {%8,%9}, {%0,%1,%2,%3};"
        : "+f"(c[0]), "+f"(c[1]), "+f"(c[2]), "+f"(c[3])
        : "r"(a[0]), "r"(a[1]), "r"(a[2]), "r"(a[3]), "r"(b[0]), "r"(b[1]));
}

// ======================= fp16 MMA GEMM ======================================
// C[128, BN] = epi(A * B). A: [M][K] row-major f16. B: [N][K] row-major f16.
// EPI: 0 fp32 C                              (scores)
//      1 f16 (x+bias)*alpha                  (q)
//      2 kv: bn<768 -> k f16 (+bias); else v_t f16 transposed (+res as bias)
//      3 f16 x                               (ao)
//      4 fp32 x+bias+res                     (o2 / out)
//      5 f16 gelu(x+bias)                    (t1)
template <int BN, int WM, int EPI>
__global__ void __launch_bounds__(256) mma_gemm(
    const f16* __restrict__ A, const f16* __restrict__ B,
    const float* __restrict__ bias, const float* __restrict__ res,
    float* __restrict__ Cf, f16* __restrict__ Ch, f16* __restrict__ C2h,
    int K, long long lda, long long ldb, long long ldc,
    int nh, long long sAb, long long sAhh, long long sBb, long long sBh,
    long long sCb, long long sChh, float alpha)
{
    extern __shared__ char smem[];
    constexpr int WN  = 8 / WM;
    constexpr int MT  = 128 / WM;      // warp m extent
    constexpr int NT  = BN / WN;       // 32
    constexpr int MI  = MT / 16;
    constexpr int NI2 = NT / 16;       // 2
    constexpr int ASZ = 128 * 80;      // bytes (pitch 80B, 32 f16 data + pad)
    constexpr int BSZ = BN * 80;
    constexpr int STG = ASZ + BSZ;

    const int tid = threadIdx.x, wid = tid >> 5, lane = tid & 31;
    const int wm = wid % WM, wn = wid / WM;
    const int z = blockIdx.z, zb = z / nh, zh = z % nh;
    A += zb * sAb + zh * sAhh;
    B += zb * sBb + zh * sBh;
    const long long coff = zb * sCb + zh * sChh;
    if (EPI == 0 || EPI == 4) Cf += coff;
    if (EPI == 1 || EPI == 3 || EPI == 5) Ch += coff;

    const long long bm = (long long)blockIdx.y * 128;
    const long long bn = (long long)blockIdx.x * BN;

    const f16* gA = A + bm * lda;
    const f16* gB = B + bn * ldb;

    float acc[MI][NI2 * 2][4];
#pragma unroll
    for (int i = 0; i < MI; i++)
#pragma unroll
        for (int j = 0; j < NI2 * 2; j++)
#pragma unroll
            for (int t = 0; t < 4; t++) acc[i][j][t] = 0.f;

    const uint32_t sb = smem_u32(smem);
    const int NC = K >> 5;

    auto fill = [&](int s, int c) {
        char* base = smem + s * STG;
        const long long k0 = (long long)c * 32;
#pragma unroll
        for (int i = tid; i < 128 * 4; i += 256) {
            int r = i >> 2, q = i & 3;
            *(int4*)(base + r * 80 + q * 16) = *(const int4*)(gA + r * lda + k0 + q * 8);
        }
#pragma unroll
        for (int i = tid; i < BN * 4; i += 256) {
            int r = i >> 2, q = i & 3;
            *(int4*)(base + ASZ + r * 80 + q * 16) = *(const int4*)(gB + r * ldb + k0 + q * 8);
        }
    };

    fill(0, 0);
    __syncthreads();

    const int a_r = (lane & 7) + ((lane >> 3) & 1) * 8;
    const int a_k = ((lane >> 4) & 1) * 8;
    const int b_r = (lane & 7) + ((lane >> 4) & 1) * 8;
    const int b_k = ((lane >> 3) & 1) * 8;

    for (int c = 0; c < NC; c++) {
        if (c + 1 < NC) fill((c + 1) & 1, c + 1);
        const uint32_t aH = sb + (c & 1) * STG;
        const uint32_t bH = aH + ASZ;
#pragma unroll
        for (int kk = 0; kk < 32; kk += 16) {
            uint32_t af[MI][4];
#pragma unroll
            for (int mi = 0; mi < MI; mi++) {
                uint32_t off = (uint32_t)(wm * MT + mi * 16 + a_r) * 80 + (kk + a_k) * 2;
                ldmx4(af[mi], aH + off);
            }
#pragma unroll
            for (int nj = 0; nj < NI2; nj++) {
                uint32_t bf[4];
                uint32_t off = (uint32_t)(wn * NT + nj * 16 + b_r) * 80 + (kk + b_k) * 2;
                ldmx4(bf, bH + off);
#pragma unroll
                for (int mi = 0; mi < MI; mi++) {
                    mma16816(acc[mi][nj * 2 + 0], af[mi], bf + 0);
                    mma16816(acc[mi][nj * 2 + 1], af[mi], bf + 2);
                }
            }
        }
        __syncthreads();
    }

    // ---- stage C into smem fp32 tile ----
    constexpr int P2 = BN + 4;
    float* tile = (float*)smem;
#pragma unroll
    for (int mi = 0; mi < MI; mi++)
#pragma unroll
        for (int j = 0; j < NI2 * 2; j++) {
            int row = wm * MT + mi * 16 + (lane >> 2);
            int col = wn * NT + j * 8 + (lane & 3) * 2;
            tile[row * P2 + col]           = acc[mi][j][0];
            tile[row * P2 + col + 1]       = acc[mi][j][1];
            tile[(row + 8) * P2 + col]     = acc[mi][j][2];
            tile[(row + 8) * P2 + col + 1] = acc[mi][j][3];
        }
    __syncthreads();

    if (EPI == 2 && bn >= 768) {
        // v region: transposed store, coalesced along tokens
        for (int idx = tid; idx < 128 * BN; idx += 256) {
            int rr = idx & 127, cc = idx >> 7;
            long long grow = bm + rr;
            long long vcol = bn + cc - 768;
            float val = tile[rr * P2 + cc] + res[vcol];
            long long b = grow / NKV, t = grow - b * NKV;
            C2h[(b * HDIM + vcol) * NKV + t] = __float2half_rn(val);
        }
        return;
    }
    for (int idx = tid; idx < 128 * BN; idx += 256) {
        int rr = idx / BN, cc = idx % BN;
        long long grow = bm + rr, gcol = bn + cc;
        float val = tile[rr * P2 + cc];
        if (EPI == 0) {
            Cf[grow * ldc + gcol] = val;
        } else if (EPI == 1) {
            Ch[grow * ldc + gcol] = __float2half_rn((val + bias[gcol]) * alpha);
        } else if (EPI == 2) {
            Ch[grow * (long long)HDIM + gcol] = __float2half_rn(val + bias[gcol]);
        } else if (EPI == 3) {
            Ch[grow * ldc + gcol] = __float2half_rn(val);
        } else if (EPI == 4) {
            Cf[grow * ldc + gcol] = val + bias[gcol] + res[grow * ldc + gcol];
        } else if (EPI == 5) {
            float u = val + bias[gcol];
            Ch[grow * ldc + gcol] =
                __float2half_rn(0.5f * u * (1.f + erff(u * 0.70710678118654752f)));
        }
    }
}

// -------------------- weight transpose + fp16 -------------------------------
__global__ void __launch_bounds__(256) wprep(
    const float* __restrict__ W, int N,
    f16* __restrict__ T, int rowOff, int ldT)
{
    __shared__ float s[32][33];
    int n0 = blockIdx.x * 32, k0 = blockIdx.y * 32;
    int tx = threadIdx.x & 31, ty = threadIdx.x >> 5;
#pragma unroll
    for (int j = 0; j < 4; j++)
        s[ty + j * 8][tx] = W[(long long)(k0 + ty + j * 8) * N + n0 + tx];
    __syncthreads();
#pragma unroll
    for (int j = 0; j < 4; j++) {
        int n = n0 + ty + j * 8, k = k0 + tx;
        T[(long long)(n + rowOff) * ldT + k] = __float2half_rn(s[tx][ty + j * 8]);
    }
}

// -------------------- LayerNorm -> fp16 --------------------------------------
template <int COLS>
__global__ void __launch_bounds__(256) ln_kernel(
    const float* __restrict__ x, const float* __restrict__ g,
    const float* __restrict__ b, f16* __restrict__ y)
{
    constexpr int PT = COLS / 256;
    const long long row = blockIdx.x;
    const float* xr = x + row * COLS;

    float v[PT];
    float s = 0.f, s2 = 0.f;
#pragma unroll
    for (int i = 0; i < PT; i++) {
        float t = xr[threadIdx.x + i * 256];
        v[i] = t; s += t; s2 += t * t;
    }
    __shared__ float red0[8], red1[8];
#pragma unroll
    for (int o = 16; o; o >>= 1) {
        s  += __shfl_xor_sync(0xffffffffu, s, o);
        s2 += __shfl_xor_sync(0xffffffffu, s2, o);
    }
    int w = threadIdx.x >> 5, l = threadIdx.x & 31;
    if (l == 0) { red0[w] = s; red1[w] = s2; }
    __syncthreads();
    s  = red0[0] + red0[1] + red0[2] + red0[3] + red0[4] + red0[5] + red0[6] + red0[7];
    s2 = red1[0] + red1[1] + red1[2] + red1[3] + red1[4] + red1[5] + red1[6] + red1[7];

    float mu  = s * (1.f / COLS);
    float var = s2 * (1.f / COLS) - mu * mu;
    float inv = rsqrtf(var + LN_EPS);
#pragma unroll
    for (int i = 0; i < PT; i++) {
        int c = threadIdx.x + i * 256;
        y[row * COLS + c] = __float2half_rn((v[i] - mu) * inv * g[c] + b[c]);
    }
}

// -------------------- softmax -> fp16 ----------------------------------------
__global__ void __launch_bounds__(256) softmax_kernel(
    const float* __restrict__ sc, f16* __restrict__ p)
{
    constexpr int PT = NKV / 256;
    size_t base = (size_t)blockIdx.x * NKV;
    float v[PT];
    float mx = -3.4e38f;
#pragma unroll
    for (int i = 0; i < PT; i++) {
        v[i] = sc[base + threadIdx.x + i * 256];
        mx = fmaxf(mx, v[i]);
    }
    __shared__ float redm[8], reds[8];
#pragma unroll
    for (int o = 16; o; o >>= 1) mx = fmaxf(mx, __shfl_xor_sync(0xffffffffu, mx, o));
    int w = threadIdx.x >> 5, l = threadIdx.x & 31;
    if (l == 0) redm[w] = mx;
    __syncthreads();
    mx = fmaxf(fmaxf(fmaxf(redm[0], redm[1]), fmaxf(redm[2], redm[3])),
               fmaxf(fmaxf(redm[4], redm[5]), fmaxf(redm[6], redm[7])));
    float s = 0.f;
#pragma unroll
    for (int i = 0; i < PT; i++) { v[i] = expf(v[i] - mx); s += v[i]; }
#pragma unroll
    for (int o = 16; o; o >>= 1) s += __shfl_xor_sync(0xffffffffu, s, o);
    if (l == 0) reds[w] = s;
    __syncthreads();
    s = reds[0] + reds[1] + reds[2] + reds[3] + reds[4] + reds[5] + reds[6] + reds[7];
    float inv = 1.f / s;
#pragma unroll
    for (int i = 0; i < PT; i++)
        p[base + threadIdx.x + i * 256] = __float2half_rn(v[i] * inv);
}

// -------------------- launch ------------------------------------------------
#define SMEM_G(BN) ((2 * (128 * 80 + (BN) * 80)) > (128 * ((BN) + 4) * 4) ? \
                    (2 * (128 * 80 + (BN) * 80)) : (128 * ((BN) + 4) * 4))

extern "C" void kernel_launch(void* const* d_in, const int* in_sizes, int n_in,
                              void* d_out, int out_size)
{
    const float* hs   = (const float*)d_in[0];
    const float* x    = (const float*)d_in[1];
    const float* Wq   = (const float*)d_in[2];
    const float* bq   = (const float*)d_in[3];
    const float* Wk   = (const float*)d_in[4];
    const float* bk   = (const float*)d_in[5];
    const float* Wv   = (const float*)d_in[6];
    const float* bv   = (const float*)d_in[7];
    const float* Wo   = (const float*)d_in[8];
    const float* bo   = (const float*)d_in[9];
    const float* W1   = (const float*)d_in[10];
    const float* b1   = (const float*)d_in[11];
    const float* W2   = (const float*)d_in[12];
    const float* b2   = (const float*)d_in[13];
    const float* gimg = (const float*)d_in[14];
    const float* bimg = (const float*)d_in[15];
    const float* ghid = (const float*)d_in[16];
    const float* bhid = (const float*)d_in[17];
    const float* gffn = (const float*)d_in[18];
    const float* bffn = (const float*)d_in[19];
    float* out = (float*)d_out;

    f16 *xn, *hn, *q, *k, *vt, *p, *ao, *hb, *t1;
    f16 *wq, *wkv, *wo, *w1, *w2;
    float *sc, *o2;
    cudaGetSymbolAddress((void**)&xn, g_xn);
    cudaGetSymbolAddress((void**)&hn, g_hn);
    cudaGetSymbolAddress((void**)&q,  g_q);
    cudaGetSymbolAddress((void**)&k,  g_k);
    cudaGetSymbolAddress((void**)&vt, g_vt);
    cudaGetSymbolAddress((void**)&sc, g_sc);
    cudaGetSymbolAddress((void**)&p,  g_p);
    cudaGetSymbolAddress((void**)&ao, g_ao);
    cudaGetSymbolAddress((void**)&o2, g_o2);
    cudaGetSymbolAddress((void**)&hb, g_hb);
    cudaGetSymbolAddress((void**)&t1, g_t1);
    cudaGetSymbolAddress((void**)&wq, g_wq);
    cudaGetSymbolAddress((void**)&wkv, g_wkv);
    cudaGetSymbolAddress((void**)&wo, g_wo);
    cudaGetSymbolAddress((void**)&w1, g_w1);
    cudaGetSymbolAddress((void**)&w2, g_w2);

    const int S128 = SMEM_G(128);
    const int S64  = SMEM_G(64);
    cudaFuncSetAttribute(mma_gemm<128, 2, 0>, cudaFuncAttributeMaxDynamicSharedMemorySize, S128);
    cudaFuncSetAttribute(mma_gemm<128, 2, 1>, cudaFuncAttributeMaxDynamicSharedMemorySize, S128);
    cudaFuncSetAttribute(mma_gemm<128, 2, 2>, cudaFuncAttributeMaxDynamicSharedMemorySize, S128);
    cudaFuncSetAttribute(mma_gemm<64,  4, 3>, cudaFuncAttributeMaxDynamicSharedMemorySize, S64);
    cudaFuncSetAttribute(mma_gemm<128, 2, 4>, cudaFuncAttributeMaxDynamicSharedMemorySize, S128);
    cudaFuncSetAttribute(mma_gemm<128, 2, 5>, cudaFuncAttributeMaxDynamicSharedMemorySize, S128);

    const int MQ = BATCH * NQ;    // 4096
    const int MK = BATCH * NKV;   // 36864

    // 0) weight prep (transpose + fp16)
    wprep<<<dim3(HDIM / 32, HDIM / 32), 256>>>(Wq, HDIM, wq, 0, HDIM);
    wprep<<<dim3(HDIM / 32, IMGD / 32), 256>>>(Wk, HDIM, wkv, 0, IMGD);
    wprep<<<dim3(HDIM / 32, IMGD / 32), 256>>>(Wv, HDIM, wkv, HDIM, IMGD);
    wprep<<<dim3(HDIM / 32, HDIM / 32), 256>>>(Wo, HDIM, wo, 0, HDIM);
    wprep<<<dim3(INTER / 32, HDIM / 32), 256>>>(W1, INTER, w1, 0, HDIM);
    wprep<<<dim3(HDIM / 32, INTER / 32), 256>>>(W2, HDIM, w2, 0, INTER);

    // 1) LayerNorms -> fp16
    ln_kernel<IMGD><<<BATCH * NKV, 256>>>(x, gimg, bimg, xn);
    ln_kernel<HDIM><<<BATCH * NQ, 256>>>(hs, ghid, bhid, hn);

    // 2) q = (hn @ Wq + bq) * SCALE
    mma_gemm<128, 2, 1><<<dim3(HDIM / 128, MQ / 128, 1), 256, S128>>>(
        hn, wq, bq, nullptr, nullptr, q, nullptr,
        HDIM, HDIM, HDIM, HDIM, 1, 0, 0, 0, 0, 0, 0, ATT_SCALE);

    // 3) [k|v] = xn @ [Wk|Wv] + [bk|bv]  -> k + v_t
    mma_gemm<128, 2, 2><<<dim3((2 * HDIM) / 128, MK / 128, 1), 256, S128>>>(
        xn, wkv, bk, bv, nullptr, k, vt,
        IMGD, IMGD, IMGD, HDIM, 1, 0, 0, 0, 0, 0, 0, 1.f);

    // 4) scores[z] = q @ k^T  -> fp32
    mma_gemm<128, 2, 0><<<dim3(NKV / 128, NQ / 128, BATCH * NHEADS), 256, S128>>>(
        q, k, nullptr, nullptr, sc, nullptr, nullptr,
        HEADD, HDIM, HDIM, NKV, NHEADS,
        (long long)NQ * HDIM, HEADD,
        (long long)NKV * HDIM, HEADD,
        (long long)NHEADS * NQ * NKV, (long long)NQ * NKV, 1.f);

    // 5) softmax -> fp16 probs
    softmax_kernel<<<BATCH * NHEADS * NQ, 256>>>(sc, p);

    // 6) ao[z] = probs @ v  (B = v_t [64][2304])
    mma_gemm<64, 4, 3><<<dim3(1, NQ / 128, BATCH * NHEADS), 256, S64>>>(
        p, vt, nullptr, nullptr, nullptr, ao, nullptr,
        NKV, NKV, NKV, HDIM, NHEADS,
        (long long)NHEADS * NQ * NKV, (long long)NQ * NKV,
        (long long)HDIM * NKV, (long long)HEADD * NKV,
        (long long)NQ * HDIM, HEADD, 1.f);

    // 7) o2 = ao @ Wo + bo + hidden_states  -> fp32
    mma_gemm<128, 2, 4><<<dim3(HDIM / 128, MQ / 128, 1), 256, S128>>>(
        ao, wo, bo, hs, o2, nullptr, nullptr,
        HDIM, HDIM, HDIM, HDIM, 1, 0, 0, 0, 0, 0, 0, 1.f);

    // 8) hb = LN(o2)
    ln_kernel<HDIM><<<BATCH * NQ, 256>>>(o2, gffn, bffn, hb);

    // 9) t1 = gelu(hb @ W1 + b1)
    mma_gemm<128, 2, 5><<<dim3(INTER / 128, MQ / 128, 1), 256, S128>>>(
        hb, w1, b1, nullptr, nullptr, t1, nullptr,
        HDIM, HDIM, HDIM, INTER, 1, 0, 0, 0, 0, 0, 0, 1.f);

    // 10) out = t1 @ W2 + b2 + o2  -> fp32
    mma_gemm<128, 2, 4><<<dim3(HDIM / 128, MQ / 128, 1), 256, S128>>>(
        t1, w2, b2, o2, out, nullptr, nullptr,
        INTER, INTER, INTER, HDIM, 1, 0, 0, 0, 0, 0, 0, 1.f);
}